// round 17
// baseline (speedup 1.0000x reference)
#include <cuda_runtime.h>
#include <cuda_bf16.h>
#include <math.h>
#include <stdint.h>

// Problem constants
#define Bb   64
#define NPG  400
#define Kk   250
#define Ff   64
#define LIN  16000
#define Hh   8000
#define Nn   (Bb*NPG)        // 25600
#define BN_EPS 1e-5f

#define KSPLIT 8             // 7 chunks of 2048 + 1 of 1664
#define G2SPLIT 8

// Scratch (device globals; no allocation allowed)
__device__ __nv_bfloat16 g_xb[Bb*LIN];      // bf16 normalized features
__device__ int   g_selidx[Bb*Kk];
__device__ float g_stanh[Bb*Kk];
__device__ __nv_bfloat16 g_hb[KSPLIT][Bb][Hh];  // split-K partials (bf16)
__device__ float g_lm[Bb];                  // per-m logit accumulators (self-resetting)
__device__ int   g_cntm[Bb];                // per-m arrival counters (self-resetting)
__device__ float g_loss;                    // loss accumulator (self-resetting)
__device__ int   g_done;                    // global arrival counter (self-resetting)

// ---------------------------------------------------------------------------
// Kernel: scores (per-thread serial dot) + bitonic top-K (warp-shuffle phases)
// Final order: value descending, index ascending on ties.
// ---------------------------------------------------------------------------
__global__ void k_sort(const float* __restrict__ feat, const float* __restrict__ w) {
    __shared__ float sv[512];
    __shared__ int   si[512];
    __shared__ float s_inv;
    int tid = threadIdx.x, b = blockIdx.x;

    if (tid == 0) {
        float s = 0.f;
        #pragma unroll
        for (int i = 0; i < Ff; i++) s += w[i] * w[i];
        s_inv = rsqrtf(s);
    }
    const float* xg = feat + (size_t)11 * Nn * Ff + (size_t)b * NPG * Ff;

    // score: thread t owns node t (16 float4 dot, no shuffles)
    float v = __int_as_float(0xff800000);   // -inf pad
    if (tid < NPG) {
        const float* x = xg + (size_t)tid * Ff;
        float s = 0.f;
        #pragma unroll
        for (int i = 0; i < 16; i++) {
            float4 xv = *(const float4*)(x + i * 4);
            float4 wv = *(const float4*)(w + i * 4);
            s += xv.x * wv.x + xv.y * wv.y + xv.z * wv.z + xv.w * wv.w;
        }
        v = s;
    }
    int idx = tid;

    // k = 2..32: all partners intra-warp -> pure shfl, no barriers
    #pragma unroll
    for (int k = 2; k <= 32; k <<= 1) {
        bool up = ((tid & k) == 0);
        #pragma unroll
        for (int j = k >> 1; j > 0; j >>= 1) {
            float vb = __shfl_xor_sync(0xffffffffu, v, j);
            int   ib = __shfl_xor_sync(0xffffffffu, idx, j);
            bool lowerLane = ((tid & j) == 0);
            bool pre = (v > vb) || (v == vb && idx < ib);    // mine precedes (desc)
            bool sw = (up == lowerLane) ? !pre : pre;
            if (sw) { v = vb; idx = ib; }
        }
    }

    // k = 64..512: smem phases for j>=32, then shfl for j<=16
    for (int k = 64; k <= 512; k <<= 1) {
        sv[tid] = v; si[tid] = idx;
        __syncthreads();
        for (int j = k >> 1; j >= 32; j >>= 1) {
            int ixj = tid ^ j;
            if (ixj > tid) {
                float va = sv[tid], vb2 = sv[ixj];
                int   ia = si[tid], ib2 = si[ixj];
                bool aFirst = (va > vb2) || (va == vb2 && ia < ib2);
                bool desc = ((tid & k) == 0);
                bool sw = desc ? !aFirst : aFirst;
                if (sw) { sv[tid] = vb2; sv[ixj] = va; si[tid] = ib2; si[ixj] = ia; }
            }
            __syncthreads();
        }
        v = sv[tid]; idx = si[tid];
        bool up = ((tid & k) == 0);
        #pragma unroll
        for (int j = 16; j > 0; j >>= 1) {
            float vb = __shfl_xor_sync(0xffffffffu, v, j);
            int   ib = __shfl_xor_sync(0xffffffffu, idx, j);
            bool lowerLane = ((tid & j) == 0);
            bool pre = (v > vb) || (v == vb && idx < ib);
            bool sw = (up == lowerLane) ? !pre : pre;
            if (sw) { v = vb; idx = ib; }
        }
    }

    if (tid < Kk) {
        g_selidx[b * Kk + tid] = idx;
        g_stanh[b * Kk + tid]  = tanhf(v * s_inv);
    }
}

// ---------------------------------------------------------------------------
// Kernel: gather + BatchNorm -> bf16 xn   grid (64, 16)
// ---------------------------------------------------------------------------
__global__ void k_bn(const float* __restrict__ feat,
                     const float* __restrict__ bn_mean, const float* __restrict__ bn_var,
                     const float* __restrict__ bn_gamma, const float* __restrict__ bn_beta) {
    int b = blockIdx.x, q = blockIdx.y, tid = threadIdx.x;
    const float* xg = feat + (size_t)11 * Nn * Ff + (size_t)b * NPG * Ff;
    int base = q * (LIN / 16);
    for (int t = tid; t < LIN / 16; t += 256) {
        int i = base + t;
        int r = i >> 6, f = i & 63;
        int idx = g_selidx[b * Kk + r];
        float st = g_stanh[b * Kk + r];
        float xv = xg[idx * Ff + f];
        float xn = (xv * st - bn_mean[i]) * rsqrtf(bn_var[i] + BN_EPS) * bn_gamma[i] + bn_beta[i];
        g_xb[(size_t)b * LIN + i] = __float2bfloat16(xn);
    }
}

// ---------------------------------------------------------------------------
// GEMM1 (frozen R12 structure):  hb[s][m][j] = sum_{k chunk s} xn[m,k]*W1[j,k]
// 128 thr (4 warps), warp tile 32m x 64j, BN=128, BK=32, 2-stage smem,
// 4 CTAs/SM. W: LDG fp32 -> bf16 regs -> STS. X: cp.async.
// grid (63, 8) = 504 CTAs, one wave. Last j-block overlaps (benign dup writes).
// Epilogue writes bf16 partials.
// ---------------------------------------------------------------------------
#define BN1   128
#define BK1   32
#define ROWB  80                    // bytes per smem row (40 halves)
#define W_BYTES (128 * ROWB)        // 10240
#define X_BYTES (64 * ROWB)         // 5120
#define STG_B   (W_BYTES + X_BYTES) // 15360

__device__ __forceinline__ void mma16816(float* d,
                                         unsigned a0, unsigned a1, unsigned a2, unsigned a3,
                                         unsigned b0, unsigned b1) {
    asm volatile(
        "mma.sync.aligned.m16n8k16.row.col.f32.bf16.bf16.f32 "
        "{%0,%1,%2,%3}, {%4,%5,%6,%7}, {%8,%9}, {%0,%1,%2,%3};\n"
        : "+f"(d[0]), "+f"(d[1]), "+f"(d[2]), "+f"(d[3])
        : "r"(a0), "r"(a1), "r"(a2), "r"(a3), "r"(b0), "r"(b1));
}

__device__ __forceinline__ void ldsm4(unsigned& r0, unsigned& r1, unsigned& r2, unsigned& r3,
                                      unsigned addr) {
    asm volatile("ldmatrix.sync.aligned.m8n8.x4.shared.b16 {%0,%1,%2,%3}, [%4];"
                 : "=r"(r0), "=r"(r1), "=r"(r2), "=r"(r3) : "r"(addr));
}

__device__ __forceinline__ void cpa16(unsigned dst, const void* src) {
    asm volatile("cp.async.cg.shared.global [%0], [%1], 16;" :: "r"(dst), "l"(src));
}

__global__ __launch_bounds__(128, 4) void k_gemm1(const float* __restrict__ W1) {
    __shared__ __align__(16) unsigned char sm[2 * STG_B];
    unsigned smbase = (unsigned)__cvta_generic_to_shared(sm);

    int tid  = threadIdx.x;
    int warp = tid >> 5, lane = tid & 31;
    int wm = warp >> 1, wj = warp & 1;          // 2x2 warp grid
    int gi = lane >> 2, qi = lane & 3;
    int jbase = blockIdx.x * BN1;
    if (jbase > Hh - BN1) jbase = Hh - BN1;     // overlap last block (dup writes benign)
    int kbase = blockIdx.y * 2048;
    int iters = (blockIdx.y == KSPLIT - 1) ? 52 : 64;  // 52*32=1664, 64*32=2048

    // W mapping: 8 float4/thread. chunk c = tid + i*128: row = (tid>>3)+i*16, c8 = tid&7
    int wrow0 = tid >> 3, wc8 = tid & 7;
    const float* wbase = W1 + (size_t)(jbase + wrow0) * LIN + kbase + wc8 * 4;
    unsigned wdst0 = smbase + (unsigned)(wrow0 * ROWB + wc8 * 8);

    // X mapping (cp.async): 2 chunks/thread. row = (tid>>2)+i*32, seg = tid&3
    int xrow0 = tid >> 2, xseg = tid & 3;
    const __nv_bfloat16* xbase = g_xb + (size_t)xrow0 * LIN + kbase + xseg * 8;
    unsigned xdst0 = smbase + (unsigned)(W_BYTES + xrow0 * ROWB + xseg * 16);

    // ldmatrix per-lane offsets (row stride 80B; conflict-free)
    unsigned offA = (unsigned)((lane & 15) * ROWB + (lane >> 4) * 16);
    unsigned offB = (unsigned)((((lane >> 4) & 1) * 8 + (lane & 7)) * ROWB + ((lane >> 3) & 1) * 16);
    unsigned aAddr0 = smbase + W_BYTES + (wm * 32) * ROWB + offA;       // mt=0
    unsigned aAddr1 = aAddr0 + 16 * ROWB;                                // mt=1
    unsigned bAddrB = smbase + (wj * 64) * ROWB + offB;                  // nt pairs at +p*16*ROWB

    float acc[2][8][4];
    #pragma unroll
    for (int a = 0; a < 2; a++)
        #pragma unroll
        for (int b = 0; b < 8; b++)
            #pragma unroll
            for (int q = 0; q < 4; q++) acc[a][b][q] = 0.f;

    // prologue: X stage 0 via cp.async; W iter 0 into registers
    #pragma unroll
    for (int i = 0; i < 2; i++)
        cpa16(xdst0 + i * (32 * ROWB), xbase + (size_t)i * 32 * LIN);
    asm volatile("cp.async.commit_group;");
    float4 wv[8];
    #pragma unroll
    for (int i = 0; i < 8; i++)
        wv[i] = *(const float4*)(wbase + (size_t)i * 16 * LIN);

    #pragma unroll 2
    for (int it = 0; it < iters; it++) {
        unsigned st = (unsigned)(it & 1) * STG_B;
        unsigned sn = (unsigned)((it + 1) & 1) * STG_B;

        // STS: convert W to bf16 (8B per chunk)
        #pragma unroll
        for (int i = 0; i < 8; i++) {
            __nv_bfloat162 p0 = __floats2bfloat162_rn(wv[i].x, wv[i].y);
            __nv_bfloat162 p1 = __floats2bfloat162_rn(wv[i].z, wv[i].w);
            asm volatile("st.shared.v2.b32 [%0], {%1,%2};"
                         :: "r"(wdst0 + st + (unsigned)(i * 16 * ROWB)),
                            "r"(*(unsigned*)&p0), "r"(*(unsigned*)&p1));
        }

        // issue next-iter loads (X cp.async into other stage; W LDG into regs)
        if (it + 1 < iters) {
            int ko = (it + 1) * BK1;
            #pragma unroll
            for (int i = 0; i < 2; i++)
                cpa16(xdst0 + sn + i * (32 * ROWB), xbase + (size_t)i * 32 * LIN + ko);
            #pragma unroll
            for (int i = 0; i < 8; i++)
                wv[i] = *(const float4*)(wbase + (size_t)i * 16 * LIN + ko);
        }
        asm volatile("cp.async.commit_group;");
        asm volatile("cp.async.wait_group 1;");   // current iter's X group done
        __syncthreads();

        // two k16 sub-chunks: per warp 6 LDSM + 16 MMA each
        #pragma unroll
        for (int kk = 0; kk < 2; kk++) {
            unsigned ko = st + (unsigned)(kk * 32);   // 16 halves = 32B
            unsigned a0[2], a1[2], a2[2], a3[2];
            ldsm4(a0[0], a1[0], a2[0], a3[0], aAddr0 + ko);
            ldsm4(a0[1], a1[1], a2[1], a3[1], aAddr1 + ko);
            #pragma unroll
            for (int p = 0; p < 4; p++) {            // n-tile pairs
                unsigned b00, b01, b10, b11;
                ldsm4(b00, b01, b10, b11, bAddrB + ko + (unsigned)(p * 16 * ROWB));
                #pragma unroll
                for (int mt = 0; mt < 2; mt++) {
                    mma16816(acc[mt][p * 2],     a0[mt], a1[mt], a2[mt], a3[mt], b00, b01);
                    mma16816(acc[mt][p * 2 + 1], a0[mt], a1[mt], a2[mt], a3[mt], b10, b11);
                }
            }
        }
        __syncthreads();
    }

    // epilogue: bf16x2 STG into split-private partials (no guard; overlap benign)
    __nv_bfloat16* hp = &g_hb[blockIdx.y][0][0];
    #pragma unroll
    for (int mt = 0; mt < 2; mt++) {
        #pragma unroll
        for (int nt = 0; nt < 8; nt++) {
            int m = wm * 32 + mt * 16 + gi;
            int j = jbase + wj * 64 + nt * 8 + qi * 2;
            __nv_bfloat162 p0 = __floats2bfloat162_rn(acc[mt][nt][0], acc[mt][nt][1]);
            __nv_bfloat162 p1 = __floats2bfloat162_rn(acc[mt][nt][2], acc[mt][nt][3]);
            *(unsigned*)(hp + (size_t)m * Hh + j)       = *(unsigned*)&p0;
            *(unsigned*)(hp + (size_t)(m + 8) * Hh + j) = *(unsigned*)&p1;
        }
    }
}

// ---------------------------------------------------------------------------
// GEMM2 + split-reduce + bias + relu + hierarchical-atomic loss.
// grid (64, 8), 128 thr. Thread t owns 8 j-cols: one LDG.128 per split.
// Tree: block -> g_lm[m] (8 arrivals) -> per-m last: softplus -> g_loss
// (64 arrivals) -> global last writes out. All counters self-reset.
// ---------------------------------------------------------------------------
__global__ void k_gemm2(const float* __restrict__ b1, const float* __restrict__ W2,
                        const float* __restrict__ b2, float* __restrict__ out) {
    int m = blockIdx.x, q = blockIdx.y, tid = threadIdx.x;
    float s = 0.f;
    if (tid < 125) {                          // 125 threads x 8 j = 1000 j
        int j = q * (Hh / G2SPLIT) + tid * 8;
        float h[8];
        #pragma unroll
        for (int i = 0; i < 8; i++) h[i] = 0.f;
        #pragma unroll
        for (int sp = 0; sp < KSPLIT; sp++) {
            uint4 hv = *(const uint4*)(&g_hb[sp][m][j]);   // 8 bf16 = 16B
            __nv_bfloat162 p0 = *(__nv_bfloat162*)&hv.x;
            __nv_bfloat162 p1 = *(__nv_bfloat162*)&hv.y;
            __nv_bfloat162 p2 = *(__nv_bfloat162*)&hv.z;
            __nv_bfloat162 p3 = *(__nv_bfloat162*)&hv.w;
            h[0] += __bfloat162float(p0.x); h[1] += __bfloat162float(p0.y);
            h[2] += __bfloat162float(p1.x); h[3] += __bfloat162float(p1.y);
            h[4] += __bfloat162float(p2.x); h[5] += __bfloat162float(p2.y);
            h[6] += __bfloat162float(p3.x); h[7] += __bfloat162float(p3.y);
        }
        #pragma unroll
        for (int half = 0; half < 2; half++) {
            float4 bv = *(const float4*)(b1 + j + half * 4);
            float4 wv = *(const float4*)(W2 + j + half * 4);
            s += fmaxf(h[half * 4 + 0] + bv.x, 0.f) * wv.x;
            s += fmaxf(h[half * 4 + 1] + bv.y, 0.f) * wv.y;
            s += fmaxf(h[half * 4 + 2] + bv.z, 0.f) * wv.z;
            s += fmaxf(h[half * 4 + 3] + bv.w, 0.f) * wv.w;
        }
    }
    #pragma unroll
    for (int o = 16; o > 0; o >>= 1) s += __shfl_down_sync(0xffffffffu, s, o);
    __shared__ float red[4];
    if ((tid & 31) == 0) red[tid >> 5] = s;
    __syncthreads();

    if (tid == 0) {
        float tot = red[0] + red[1] + red[2] + red[3];
        atomicAdd(&g_lm[m], tot);
        __threadfence();
        int old = atomicAdd(&g_cntm[m], 1);
        if (old == G2SPLIT - 1) {
            // last block of this m: all adds to g_lm[m] visible
            float l = atomicAdd(&g_lm[m], 0.f) + b2[0];
            float per = (l > 0.f) ? log1pf(expf(-l)) : (log1pf(expf(l)) - l);
            atomicAdd(&g_loss, per);
            __threadfence();
            int o2 = atomicAdd(&g_done, 1);
            if (o2 == Bb - 1) {
                out[0] = atomicAdd(&g_loss, 0.f) * (1.0f / Bb);
                g_loss = 0.f;               // reset for next graph replay
                g_done = 0;
            }
            g_lm[m] = 0.f;                  // self-reset
            g_cntm[m] = 0;
        }
    }
}

// ---------------------------------------------------------------------------
extern "C" void kernel_launch(void* const* d_in, const int* in_sizes, int n_in,
                              void* d_out, int out_size) {
    const float* feat     = (const float*)d_in[0];
    const float* w        = (const float*)d_in[3];
    const float* bn_gamma = (const float*)d_in[4];
    const float* bn_beta  = (const float*)d_in[5];
    const float* bn_mean  = (const float*)d_in[6];
    const float* bn_var   = (const float*)d_in[7];
    const float* W1       = (const float*)d_in[8];
    const float* b1       = (const float*)d_in[9];
    const float* W2       = (const float*)d_in[10];
    const float* b2       = (const float*)d_in[11];

    k_sort<<<Bb, 512>>>(feat, w);
    dim3 gbn(Bb, 16);
    k_bn<<<gbn, 256>>>(feat, bn_mean, bn_var, bn_gamma, bn_beta);
    dim3 g1(63, KSPLIT);   // 504 CTAs, 4/SM -> one wave
    k_gemm1<<<g1, 128>>>(W1);
    dim3 g2(Bb, G2SPLIT);
    k_gemm2<<<g2, 128>>>(b1, W2, b2, (float*)d_out);
}